// round 1
// baseline (speedup 1.0000x reference)
#include <cuda_runtime.h>
#include <cstdint>

// HoyerSparsityLoss: N=1024 anchors, 1024 pos + 1024 neg targets, D=256.
// loss_i = log(sum_t exp(hoyer(i,t)/T)) - hoyer(i,i_pos)/T ; out = mean_i loss_i
// hoyer = (sqrt(D) - l1/l2) / (sqrt(D)-1), l2 = sqrt(sum d^2)+1e-8, T=0.05.

#define TILE  64
#define DK    32
#define DVAL  256
#define NANCH 1024

__device__ float g_rowsum[NANCH];
__device__ float g_diag[NANCH];

__device__ __forceinline__ unsigned long long fadd2(unsigned long long a, unsigned long long b) {
    unsigned long long r;
    asm("add.rn.f32x2 %0, %1, %2;" : "=l"(r) : "l"(a), "l"(b));
    return r;
}
__device__ __forceinline__ unsigned long long ffma2(unsigned long long a, unsigned long long b, unsigned long long c) {
    unsigned long long r;
    asm("fma.rn.f32x2 %0, %1, %2, %3;" : "=l"(r) : "l"(a), "l"(b), "l"(c));
    return r;
}
__device__ __forceinline__ unsigned long long pack2(float lo, float hi) {
    unsigned long long r;
    asm("mov.b64 %0, {%1, %2};" : "=l"(r) : "f"(lo), "f"(hi));
    return r;
}

__global__ void zero_k() { g_rowsum[threadIdx.x] = 0.0f; }

__global__ __launch_bounds__(256) void hoyer_k(const float* __restrict__ anchor,
                                               const float* __restrict__ pos,
                                               const float* __restrict__ neg) {
    // As: pre-splatted anchor values (both f32x2 lanes = a) -> packed math over j.
    // Bs: negated target values so diff = a + (-b) is a single add.
    __shared__ float2 As[DK][TILE];
    __shared__ float  Bs[DK][TILE];

    const int bi = blockIdx.x;            // anchor tile (16 tiles of 64)
    const int bj = blockIdx.y;            // target tile (32 tiles of 64: 16 pos, 16 neg)
    const bool is_pos = (bj < 16);
    const float* tgt = is_pos ? pos : neg;
    const int joff = (is_pos ? bj : bj - 16) * TILE;
    const int ioff = bi * TILE;
    const int tid = threadIdx.x;
    const int tx = tid & 15;              // j direction (4 targets/thread, packed as 2x f32x2)
    const int ty = tid >> 4;              // i direction (4 anchors/thread)

    unsigned long long l1[4][2], l2[4][2];
#pragma unroll
    for (int t = 0; t < 4; ++t)
#pragma unroll
        for (int jp = 0; jp < 2; ++jp) { l1[t][jp] = 0ull; l2[t][jp] = 0ull; }

    for (int c = 0; c < DVAL / DK; ++c) {
        // Load 64 rows x 32 d of A and B: 512 float4 each, 2 per thread.
#pragma unroll
        for (int r = 0; r < 2; ++r) {
            const int idx = tid + r * 256;
            const int row = idx >> 3;          // 8 float4 per row
            const int dd  = (idx & 7) * 4;
            const float4 va = *(const float4*)(anchor + (size_t)(ioff + row) * DVAL + c * DK + dd);
            As[dd + 0][row] = make_float2(va.x, va.x);
            As[dd + 1][row] = make_float2(va.y, va.y);
            As[dd + 2][row] = make_float2(va.z, va.z);
            As[dd + 3][row] = make_float2(va.w, va.w);
            const float4 vb = *(const float4*)(tgt + (size_t)(joff + row) * DVAL + c * DK + dd);
            Bs[dd + 0][row] = -vb.x;
            Bs[dd + 1][row] = -vb.y;
            Bs[dd + 2][row] = -vb.z;
            Bs[dd + 3][row] = -vb.w;
        }
        __syncthreads();

#pragma unroll
        for (int dk = 0; dk < DK; ++dk) {
            unsigned long long a2[4], b2[2];
#pragma unroll
            for (int t = 0; t < 4; ++t)
                a2[t] = *(const unsigned long long*)&As[dk][ty * 4 + t];
            const float4 bv = *(const float4*)&Bs[dk][tx * 4];
            b2[0] = pack2(bv.x, bv.y);
            b2[1] = pack2(bv.z, bv.w);
#pragma unroll
            for (int t = 0; t < 4; ++t) {
#pragma unroll
                for (int jp = 0; jp < 2; ++jp) {
                    const unsigned long long d = fadd2(a2[t], b2[jp]);       // a - b (fma pipe)
                    l2[t][jp] = ffma2(d, d, l2[t][jp]);                      // fma pipe
                    const unsigned long long ad = d & 0x7FFFFFFF7FFFFFFFULL; // |.| (2x LOP3, alu pipe)
                    l1[t][jp] = fadd2(l1[t][jp], ad);                        // fma pipe
                }
            }
        }
        __syncthreads();
    }

    // Epilogue: hoyer -> exp -> row partial sums (+ diag capture for pos tiles).
    const float inv15 = 1.0f / 15.0f;
#pragma unroll
    for (int t = 0; t < 4; ++t) {
        const int gi = ioff + ty * 4 + t;
        float rsum = 0.0f;
#pragma unroll
        for (int jp = 0; jp < 2; ++jp) {
#pragma unroll
            for (int ln = 0; ln < 2; ++ln) {
                const float s1 = __uint_as_float((unsigned)(l1[t][jp] >> (ln * 32)));
                const float s2 = __uint_as_float((unsigned)(l2[t][jp] >> (ln * 32)));
                // l2 ~ 22.6 here; 1e-8 eps is relatively 4e-10 -> safe to drop.
                const float hy = (16.0f - s1 * rsqrtf(s2)) * inv15;
                rsum += __expf(hy * 20.0f);   // hy / 0.05
                if (is_pos) {
                    const int gj = joff + tx * 4 + jp * 2 + ln;
                    if (gj == gi) g_diag[gi] = hy;   // single writer per i
                }
            }
        }
        // Reduce across tx (16 lanes within each half-warp); ty stays separated.
#pragma unroll
        for (int m = 1; m < 16; m <<= 1)
            rsum += __shfl_xor_sync(0xffffffffu, rsum, m);
        if (tx == 0) atomicAdd(&g_rowsum[gi], rsum);
    }
}

__global__ void final_k(float* out) {
    __shared__ float red[NANCH];
    const int i = threadIdx.x;
    float v = logf(g_rowsum[i]) - g_diag[i] * 20.0f;
    red[i] = v;
    __syncthreads();
    for (int s = 512; s > 0; s >>= 1) {
        if (i < s) red[i] += red[i + s];
        __syncthreads();
    }
    if (i == 0) out[0] = red[0] * (1.0f / 1024.0f);
}

extern "C" void kernel_launch(void* const* d_in, const int* in_sizes, int n_in,
                              void* d_out, int out_size) {
    const float* anchor = (const float*)d_in[0];
    const float* pos    = (const float*)d_in[1];
    const float* neg    = (const float*)d_in[2];

    zero_k<<<1, NANCH>>>();
    dim3 grid(16, 32);        // 16 anchor tiles x (16 pos + 16 neg) target tiles
    hoyer_k<<<grid, 256>>>(anchor, pos, neg);
    final_k<<<1, NANCH>>>((float*)d_out);
}

// round 2
// speedup vs baseline: 1.1154x; 1.1154x over previous
#include <cuda_runtime.h>
#include <cstdint>

// HoyerSparsityLoss: N=1024 anchors, 1024 pos + 1024 neg targets, D=256.
// hoyer = (16 - l1/l2)/15, T=0.05. loss_i = log(sum_t exp(h/T)) - h_ii/T.

#define TI    128      // i-tile (anchors) per block
#define TJ    64       // j-tile (targets) per block
#define DK    32       // d-chunk
#define DVAL  256
#define NANCH 1024

__device__ float g_rowsum[NANCH];
__device__ float g_diag[NANCH];

typedef unsigned long long ull;

__device__ __forceinline__ ull fadd2(ull a, ull b) {
    ull r; asm("add.rn.f32x2 %0, %1, %2;" : "=l"(r) : "l"(a), "l"(b)); return r;
}
__device__ __forceinline__ ull ffma2(ull a, ull b, ull c) {
    ull r; asm("fma.rn.f32x2 %0, %1, %2, %3;" : "=l"(r) : "l"(a), "l"(b), "l"(c)); return r;
}
__device__ __forceinline__ ull pack2(float lo, float hi) {
    ull r; asm("mov.b64 %0, {%1, %2};" : "=l"(r) : "f"(lo), "f"(hi)); return r;
}
__device__ __forceinline__ ull splat2(float v) {
    ull r; asm("mov.b64 %0, {%1, %1};" : "=l"(r) : "f"(v)); return r;
}

#define CP_ASYNC16(smem_u32, gptr) \
    asm volatile("cp.async.cg.shared.global [%0], [%1], 16;" :: "r"(smem_u32), "l"(gptr))
#define CP_COMMIT() asm volatile("cp.async.commit_group;")
#define CP_WAIT(n)  asm volatile("cp.async.wait_group %0;" :: "n"(n))

__global__ void zero_k() { g_rowsum[threadIdx.x] = 0.0f; }

__global__ __launch_bounds__(256, 2) void hoyer_k(const float* __restrict__ anchor,
                                                  const float* __restrict__ pos,
                                                  const float* __restrict__ neg) {
    // float4-group layout: As[buf][dg][row] holds d = dg*4..dg*4+3 for `row`.
    __shared__ float4 As[2][8][TI];   // 2*8*128*16 = 32 KB
    __shared__ float4 Bs[2][8][TJ];   // 2*8*64*16  = 16 KB

    const int bi = blockIdx.x;            // 8 i-tiles of 128
    const int bj = blockIdx.y;            // 32 j-tiles of 64 (16 pos + 16 neg)
    const bool is_pos = (bj < 16);
    const float* tgt = is_pos ? pos : neg;
    const int joff = (is_pos ? bj : bj - 16) * TJ;
    const int ioff = bi * TI;
    const int tid = threadIdx.x;
    const int tx = tid & 15;              // j: 4 targets (tx*4 .. +3)
    const int ty = tid >> 4;              // i: 8 anchors (ty*8 .. +7)

    ull l1[8][2], l2[8][2];
#pragma unroll
    for (int t = 0; t < 8; ++t) { l1[t][0]=l1[t][1]=l2[t][0]=l2[t][1]=0ull; }

    // ---- async loaders: warp reads 32 consecutive rows (conflict-free STS.128)
    auto load_chunk = [&](int c, int buf) {
#pragma unroll
        for (int r = 0; r < 4; ++r) {                 // A: 1024 float4
            const int idx = tid + r * 256;
            const int row = idx & 127, dg = idx >> 7;
            const float* g = anchor + (size_t)(ioff + row) * DVAL + c * DK + dg * 4;
            CP_ASYNC16((unsigned)__cvta_generic_to_shared(&As[buf][dg][row]), g);
        }
#pragma unroll
        for (int r = 0; r < 2; ++r) {                 // B: 512 float4
            const int idx = tid + r * 256;
            const int row = idx & 63, dg = idx >> 6;
            const float* g = tgt + (size_t)(joff + row) * DVAL + c * DK + dg * 4;
            CP_ASYNC16((unsigned)__cvta_generic_to_shared(&Bs[buf][dg][row]), g);
        }
    };

    load_chunk(0, 0);
    CP_COMMIT();

    for (int c = 0; c < DVAL / DK; ++c) {
        const int buf = c & 1;
        if (c + 1 < DVAL / DK) { load_chunk(c + 1, buf ^ 1); CP_COMMIT(); CP_WAIT(1); }
        else                   { CP_WAIT(0); }
        __syncthreads();

#pragma unroll
        for (int dg = 0; dg < 8; ++dg) {
            // B: 4 targets x 4 dk, packed into (j0,j1) / (j2,j3) pairs, pre-negated.
            float4 b4[4];
#pragma unroll
            for (int j4 = 0; j4 < 4; ++j4) b4[j4] = Bs[buf][dg][tx * 4 + j4];
            ull bp[4][2];
#pragma unroll
            for (int dk = 0; dk < 4; ++dk) {
                const float* f0 = (const float*)&b4[0];
                const float* f1 = (const float*)&b4[1];
                const float* f2 = (const float*)&b4[2];
                const float* f3 = (const float*)&b4[3];
                bp[dk][0] = pack2(f0[dk], f1[dk]) ^ 0x8000000080000000ULL;
                bp[dk][1] = pack2(f2[dk], f3[dk]) ^ 0x8000000080000000ULL;
            }
#pragma unroll
            for (int t = 0; t < 8; ++t) {
                const float4 a4 = As[buf][dg][ty * 8 + t];
                const float* af = (const float*)&a4;
#pragma unroll
                for (int dk = 0; dk < 4; ++dk) {
                    const ull av = splat2(af[dk]);
#pragma unroll
                    for (int jp = 0; jp < 2; ++jp) {
                        const ull d = fadd2(av, bp[dk][jp]);           // a - b     (fma)
                        l2[t][jp] = ffma2(d, d, l2[t][jp]);            // sum d^2   (fma)
                        const ull ad = d & 0x7FFFFFFF7FFFFFFFULL;      // |d|       (alu)
                        l1[t][jp] = fadd2(l1[t][jp], ad);              // sum |d|   (fma)
                    }
                }
            }
        }
        __syncthreads();
    }

    // ---- epilogue: hoyer -> exp -> row sums (+ diagonal capture on pos tiles)
    const float inv15 = 1.0f / 15.0f;
#pragma unroll
    for (int t = 0; t < 8; ++t) {
        const int gi = ioff + ty * 8 + t;
        float rsum = 0.0f;
#pragma unroll
        for (int jp = 0; jp < 2; ++jp) {
#pragma unroll
            for (int ln = 0; ln < 2; ++ln) {
                const float s1 = __uint_as_float((unsigned)(l1[t][jp] >> (ln * 32)));
                const float s2 = __uint_as_float((unsigned)(l2[t][jp] >> (ln * 32)));
                // l2 ~ 22.6 here; the 1e-8 eps is relatively 4e-10 -> dropped.
                const float hy = (16.0f - s1 * rsqrtf(s2)) * inv15;
                rsum += __expf(hy * 20.0f);   // hy / 0.05
                if (is_pos) {
                    const int gj = joff + tx * 4 + jp * 2 + ln;
                    if (gj == gi) g_diag[gi] = hy;   // unique writer per i
                }
            }
        }
#pragma unroll
        for (int m = 1; m < 16; m <<= 1)
            rsum += __shfl_xor_sync(0xffffffffu, rsum, m);
        if (tx == 0) atomicAdd(&g_rowsum[gi], rsum);
    }
}

__global__ void final_k(float* out) {
    __shared__ float red[NANCH];
    const int i = threadIdx.x;
    red[i] = logf(g_rowsum[i]) - g_diag[i] * 20.0f;
    __syncthreads();
    for (int s = 512; s > 0; s >>= 1) {
        if (i < s) red[i] += red[i + s];
        __syncthreads();
    }
    if (i == 0) out[0] = red[0] * (1.0f / 1024.0f);
}

extern "C" void kernel_launch(void* const* d_in, const int* in_sizes, int n_in,
                              void* d_out, int out_size) {
    const float* anchor = (const float*)d_in[0];
    const float* pos    = (const float*)d_in[1];
    const float* neg    = (const float*)d_in[2];

    zero_k<<<1, NANCH>>>();
    dim3 grid(NANCH / TI, 32);   // 8 x (16 pos + 16 neg)
    hoyer_k<<<grid, 256>>>(anchor, pos, neg);
    final_k<<<1, NANCH>>>((float*)d_out);
}

// round 4
// speedup vs baseline: 1.1300x; 1.0131x over previous
#include <cuda_runtime.h>
#include <cstdint>

// HoyerSparsityLoss: N=1024 anchors, 1024 pos + 1024 neg targets, D=256.
// hoyer = (16 - l1/l2)/15, T=0.05. loss_i = log(sum_t exp(h/T)) - h_ii/T.
// f32x2 lanes packed over the d dimension: A and B both load packed, no splats.

#define TI    64
#define TJ    64
#define DK    32       // d per double-buffered chunk
#define DVAL  256
#define NANCH 1024

__device__ float g_rowsum[NANCH];   // zero-init at load; final_k re-zeroes after use
__device__ float g_diag[NANCH];

typedef unsigned long long ull;

__device__ __forceinline__ ull fadd2(ull a, ull b) {
    ull r; asm("add.rn.f32x2 %0, %1, %2;" : "=l"(r) : "l"(a), "l"(b)); return r;
}
__device__ __forceinline__ ull ffma2(ull a, ull b, ull c) {
    ull r; asm("fma.rn.f32x2 %0, %1, %2, %3;" : "=l"(r) : "l"(a), "l"(b), "l"(c)); return r;
}

#define CP_ASYNC16(smem_u32, gptr) \
    asm volatile("cp.async.cg.shared.global [%0], [%1], 16;" :: "r"(smem_u32), "l"(gptr))
#define CP_COMMIT() asm volatile("cp.async.commit_group;")
#define CP_WAIT(n)  asm volatile("cp.async.wait_group %0;" :: "n"(n))

__global__ __launch_bounds__(256, 2) void hoyer_k(const float* __restrict__ anchor,
                                                  const float* __restrict__ pos,
                                                  const float* __restrict__ neg) {
    // As[buf][c4][row]: float4 of d = c*32 + c4*4 .. +3 for anchor row.
    __shared__ float4 As[2][8][TI];   // 16 KB
    __shared__ float4 Bs[2][8][TJ];   // 16 KB

    const int bi = blockIdx.x;             // 16 i-tiles of 64
    const int bj = blockIdx.y;             // 32 j-tiles of 64 (16 pos + 16 neg)
    const bool is_pos = (bj < 16);
    const float* tgt = is_pos ? pos : neg;
    const int joff = (is_pos ? bj : bj - 16) * TJ;
    const int ioff = bi * TI;
    const int tid = threadIdx.x;
    const int tx = tid & 15;               // j: handles j = tx + 16*jj, jj=0..3
    const int ty = tid >> 4;               // i: handles i = ty + 16*ii, ii=0..3

    // Packed-over-d accumulators per (ii,jj) cell.
    ull l1[4][4], l2[4][4];
#pragma unroll
    for (int ii = 0; ii < 4; ++ii)
#pragma unroll
        for (int jj = 0; jj < 4; ++jj) { l1[ii][jj] = 0ull; l2[ii][jj] = 0ull; }

    ull neg1;  // packed {-1.0f, -1.0f}
    asm("mov.b64 %0, {%1, %1};" : "=l"(neg1) : "f"(-1.0f));

    auto load_chunk = [&](int c, int buf) {
#pragma unroll
        for (int r = 0; r < 2; ++r) {          // 512 float4 each for A and B
            const int idx = tid + r * 256;
            const int row = idx & 63, c4 = idx >> 6;
            const float* ga = anchor + (size_t)(ioff + row) * DVAL + c * DK + c4 * 4;
            CP_ASYNC16((unsigned)__cvta_generic_to_shared(&As[buf][c4][row]), ga);
            const float* gb = tgt + (size_t)(joff + row) * DVAL + c * DK + c4 * 4;
            CP_ASYNC16((unsigned)__cvta_generic_to_shared(&Bs[buf][c4][row]), gb);
        }
    };

    load_chunk(0, 0);
    CP_COMMIT();

    for (int c = 0; c < DVAL / DK; ++c) {
        const int buf = c & 1;
        if (c + 1 < DVAL / DK) { load_chunk(c + 1, buf ^ 1); CP_COMMIT(); CP_WAIT(1); }
        else                   { CP_WAIT(0); }
        __syncthreads();

#pragma unroll
        for (int c4 = 0; c4 < 8; ++c4) {
            float4 b[4];
#pragma unroll
            for (int jj = 0; jj < 4; ++jj) b[jj] = Bs[buf][c4][tx + 16 * jj];  // conflict-free
#pragma unroll
            for (int ii = 0; ii < 4; ++ii) {
                const float4 a = As[buf][c4][ty + 16 * ii];                    // broadcast
                const ull a01 = ((const ull*)&a)[0];
                const ull a23 = ((const ull*)&a)[1];
#pragma unroll
                for (int jj = 0; jj < 4; ++jj) {
                    const ull b01 = ((const ull*)&b[jj])[0];
                    const ull b23 = ((const ull*)&b[jj])[1];
                    ull d = ffma2(b01, neg1, a01);                  // a - b        (fma)
                    l2[ii][jj] = ffma2(d, d, l2[ii][jj]);           // sum d^2      (fma)
                    l1[ii][jj] = fadd2(l1[ii][jj],
                                       d & 0x7FFFFFFF7FFFFFFFULL);  // sum |d| (alu+fma)
                    d = ffma2(b23, neg1, a23);
                    l2[ii][jj] = ffma2(d, d, l2[ii][jj]);
                    l1[ii][jj] = fadd2(l1[ii][jj],
                                       d & 0x7FFFFFFF7FFFFFFFULL);
                }
            }
        }
        __syncthreads();
    }

    // Epilogue: horizontal add -> hoyer -> exp -> row sums (+ diagonal on pos tiles)
    const float inv15 = 1.0f / 15.0f;
#pragma unroll
    for (int ii = 0; ii < 4; ++ii) {
        const int gi = ioff + ty + 16 * ii;
        float rsum = 0.0f;
#pragma unroll
        for (int jj = 0; jj < 4; ++jj) {
            const float s1 = __uint_as_float((unsigned)l1[ii][jj]) +
                             __uint_as_float((unsigned)(l1[ii][jj] >> 32));
            const float s2 = __uint_as_float((unsigned)l2[ii][jj]) +
                             __uint_as_float((unsigned)(l2[ii][jj] >> 32));
            // l2 ~ 22.6; the 1e-8 eps is relatively 4e-10 -> dropped.
            const float hy = (16.0f - s1 * rsqrtf(s2)) * inv15;
            rsum += __expf(hy * 20.0f);     // hy / T, T=0.05
            if (is_pos && (joff + tx + 16 * jj) == gi) g_diag[gi] = hy;  // unique writer
        }
#pragma unroll
        for (int m = 1; m < 16; m <<= 1)
            rsum += __shfl_xor_sync(0xffffffffu, rsum, m);
        if (tx == 0) atomicAdd(&g_rowsum[gi], rsum);
    }
}

__global__ void final_k(float* out) {
    __shared__ float warp_part[32];
    const int i = threadIdx.x;
    float v = __logf(g_rowsum[i]) - g_diag[i] * 20.0f;
    g_rowsum[i] = 0.0f;                 // reset for next graph replay
#pragma unroll
    for (int m = 16; m > 0; m >>= 1) v += __shfl_xor_sync(0xffffffffu, v, m);
    if ((i & 31) == 0) warp_part[i >> 5] = v;
    __syncthreads();
    if (i < 32) {
        float w = warp_part[i];
#pragma unroll
        for (int m = 16; m > 0; m >>= 1) w += __shfl_xor_sync(0xffffffffu, w, m);
        if (i == 0) out[0] = w * (1.0f / 1024.0f);
    }
}

extern "C" void kernel_launch(void* const* d_in, const int* in_sizes, int n_in,
                              void* d_out, int out_size) {
    const float* anchor = (const float*)d_in[0];
    const float* pos    = (const float*)d_in[1];
    const float* neg    = (const float*)d_in[2];

    dim3 grid(NANCH / TI, 32);   // 16 x (16 pos + 16 neg)
    hoyer_k<<<grid, 256>>>(anchor, pos, neg);
    final_k<<<1, NANCH>>>((float*)d_out);
}

// round 5
// speedup vs baseline: 1.2772x; 1.1302x over previous
#include <cuda_runtime.h>
#include <cstdint>

// HoyerSparsityLoss: N=1024 anchors, 1024 pos + 1024 neg targets, D=256.
// hoyer = (16 - l1/l2)/15, T=0.05. loss_i = log(sum_t exp(h/T)) - h_ii/T.
// Single fused kernel: tile pass + fence/counter last-block final reduction.
// fma-pipe diet: diff and l1-accum as FFMA-imm (rt_SMSP=1), l2-accum 3-reg FFMA.

#define TI    64
#define TJ    64
#define DK    32
#define DVAL  256
#define NANCH 1024
#define NBLK  512          // 16 i-tiles x 32 j-tiles

__device__ float    g_rowsum[NANCH];  // zero-init at load; last block re-zeroes
__device__ float    g_diag[NANCH];
__device__ unsigned g_count;          // zero-init; last block resets

// 1 ulp below 1.0: forces FFMA-imm (ptxas cannot fold to FADD). d error ~6e-8 rel.
#define C_NEG (-0.99999994f)

#define CP_ASYNC16(smem_u32, gptr) \
    asm volatile("cp.async.cg.shared.global [%0], [%1], 16;" :: "r"(smem_u32), "l"(gptr))
#define CP_COMMIT() asm volatile("cp.async.commit_group;")
#define CP_WAIT(n)  asm volatile("cp.async.wait_group %0;" :: "n"(n))

__global__ __launch_bounds__(256, 2) void hoyer_k(const float* __restrict__ anchor,
                                                  const float* __restrict__ pos,
                                                  const float* __restrict__ neg,
                                                  float* __restrict__ out) {
    __shared__ float4 As[2][8][TI];   // 16 KB
    __shared__ float4 Bs[2][8][TJ];   // 16 KB

    const int bi = blockIdx.x;             // 16 i-tiles
    const int bj = blockIdx.y;             // 32 j-tiles (16 pos + 16 neg)
    const bool is_pos = (bj < 16);
    const float* tgt = is_pos ? pos : neg;
    const int joff = (is_pos ? bj : bj - 16) * TJ;
    const int ioff = bi * TI;
    const int tid = threadIdx.x;
    const int tx = tid & 15;               // j = tx + 16*jj
    const int ty = tid >> 4;               // i = ty + 16*ii

    float l1[4][4], l2[4][4];
#pragma unroll
    for (int ii = 0; ii < 4; ++ii)
#pragma unroll
        for (int jj = 0; jj < 4; ++jj) { l1[ii][jj] = 0.0f; l2[ii][jj] = 0.0f; }

    auto load_chunk = [&](int c, int buf) {
#pragma unroll
        for (int r = 0; r < 2; ++r) {
            const int idx = tid + r * 256;
            const int row = idx & 63, c4 = idx >> 6;
            const float* ga = anchor + (size_t)(ioff + row) * DVAL + c * DK + c4 * 4;
            CP_ASYNC16((unsigned)__cvta_generic_to_shared(&As[buf][c4][row]), ga);
            const float* gb = tgt + (size_t)(joff + row) * DVAL + c * DK + c4 * 4;
            CP_ASYNC16((unsigned)__cvta_generic_to_shared(&Bs[buf][c4][row]), gb);
        }
    };

    load_chunk(0, 0);
    CP_COMMIT();

    for (int c = 0; c < DVAL / DK; ++c) {
        const int buf = c & 1;
        if (c + 1 < DVAL / DK) { load_chunk(c + 1, buf ^ 1); CP_COMMIT(); CP_WAIT(1); }
        else                   { CP_WAIT(0); }
        __syncthreads();

#pragma unroll
        for (int c4 = 0; c4 < 8; ++c4) {
            float4 bv[4];
#pragma unroll
            for (int jj = 0; jj < 4; ++jj) bv[jj] = Bs[buf][c4][tx + 16 * jj];
#pragma unroll
            for (int ii = 0; ii < 4; ++ii) {
                const float4 av = As[buf][c4][ty + 16 * ii];   // broadcast
                const float* af = (const float*)&av;
#pragma unroll
                for (int jj = 0; jj < 4; ++jj) {
                    const float* bf = (const float*)&bv[jj];
#pragma unroll
                    for (int dk = 0; dk < 4; ++dk) {
                        const float d = fmaf(bf[dk], C_NEG, af[dk]);   // FFMA-imm (rt1)
                        l2[ii][jj] = fmaf(d, d, l2[ii][jj]);           // FFMA     (rt2)
                        l1[ii][jj] = fmaf(fabsf(d), 2.0f, l1[ii][jj]); // FFMA-imm (rt1)
                    }
                }
            }
        }
        __syncthreads();
    }

    // Epilogue: hoyer -> exp -> row sums (+ diagonal on pos tiles). l1 carries x2.
    const float inv15 = 1.0f / 15.0f;
#pragma unroll
    for (int ii = 0; ii < 4; ++ii) {
        const int gi = ioff + ty + 16 * ii;
        float rsum = 0.0f;
#pragma unroll
        for (int jj = 0; jj < 4; ++jj) {
            // l2 ~ 510 here; 1e-8 eps is relatively ~4e-10 -> dropped.
            const float hy = (16.0f - l1[ii][jj] * 0.5f * rsqrtf(l2[ii][jj])) * inv15;
            rsum += __expf(hy * 20.0f);     // hy / T, T = 0.05
            if (is_pos && (joff + tx + 16 * jj) == gi) g_diag[gi] = hy;  // unique writer
        }
#pragma unroll
        for (int m = 1; m < 16; m <<= 1)
            rsum += __shfl_xor_sync(0xffffffffu, rsum, m);
        if (tx == 0) atomicAdd(&g_rowsum[gi], rsum);
    }

    // ---- last-block final reduction (replaces the final_k launch) ----
    __shared__ bool is_last;
    __threadfence();
    if (tid == 0) is_last = (atomicAdd(&g_count, 1u) == NBLK - 1);
    __syncthreads();
    if (!is_last) return;
    __threadfence();   // acquire: all blocks' rowsum/diag now visible

    float acc = 0.0f;
#pragma unroll
    for (int r = 0; r < 4; ++r) {
        const int i = tid + r * 256;
        acc += __logf(g_rowsum[i]) - g_diag[i] * 20.0f;
        g_rowsum[i] = 0.0f;               // reset for next graph replay
    }
#pragma unroll
    for (int m = 16; m > 0; m >>= 1) acc += __shfl_xor_sync(0xffffffffu, acc, m);

    __shared__ float warp_part[8];
    if ((tid & 31) == 0) warp_part[tid >> 5] = acc;
    __syncthreads();
    if (tid < 32) {
        float w = (tid < 8) ? warp_part[tid] : 0.0f;
#pragma unroll
        for (int m = 4; m > 0; m >>= 1) w += __shfl_xor_sync(0xffffffffu, w, m);
        if (tid == 0) { out[0] = w * (1.0f / 1024.0f); g_count = 0; }
    }
}

extern "C" void kernel_launch(void* const* d_in, const int* in_sizes, int n_in,
                              void* d_out, int out_size) {
    const float* anchor = (const float*)d_in[0];
    const float* pos    = (const float*)d_in[1];
    const float* neg    = (const float*)d_in[2];

    dim3 grid(NANCH / TI, 32);   // 16 x (16 pos + 16 neg) = 512 blocks
    hoyer_k<<<grid, 256>>>(anchor, pos, neg, (float*)d_out);
}